// round 1
// baseline (speedup 1.0000x reference)
#include <cuda_runtime.h>

#define BSZ 1024
#define HD  512
#define DH  256

typedef unsigned long long u64;

// Scratch (no device allocation allowed -> __device__ globals)
__device__ float g_qproj[BSZ * HD];   // q_proj + ba, [B, H]
__device__ float g_s[BSZ * DH];       // attention logits, [B, D]

// ---------------------------------------------------------------------------
// helpers: packed f32x2 FMA (sm_100+), fast accurate tanh
// ---------------------------------------------------------------------------
__device__ __forceinline__ u64 pk2(float lo, float hi) {
    u64 r;
    asm("mov.b64 %0, {%1, %2};" : "=l"(r) : "f"(lo), "f"(hi));
    return r;
}
__device__ __forceinline__ void fma2(u64 &d, u64 a, u64 b) {
    asm("fma.rn.f32x2 %0, %1, %2, %0;" : "+l"(d) : "l"(a), "l"(b));
}
__device__ __forceinline__ float2 upk(u64 v) {
    float2 f;
    asm("mov.b64 {%0, %1}, %2;" : "=f"(f.x), "=f"(f.y) : "l"(v));
    return f;
}
// tanh(x) = 1 - 2/(exp(2x)+1); __expf is MUFU.EX2-based (rel err ~2^-22).
// Saturates gracefully: exp->inf gives 1, exp->0 gives -1. Abs err ~1e-7.
__device__ __forceinline__ float fast_tanh(float x) {
    float e = __expf(2.0f * x);
    return 1.0f - 2.0f / (e + 1.0f);
}

// ---------------------------------------------------------------------------
// K0: zero the logit accumulator
// ---------------------------------------------------------------------------
__global__ void zero_s_kernel() {
    int i = blockIdx.x * blockDim.x + threadIdx.x;
    if (i < BSZ * DH) g_s[i] = 0.0f;
}

// ---------------------------------------------------------------------------
// K1: q_proj[b,g] = sum_j [h_tilde;c_t][b,j] * Waq[g,j]  + ba[g]
//     GEMM M=1024 N=512 K=1024, 64x64x16 tiles, 4x4 microtile
// ---------------------------------------------------------------------------
__global__ __launch_bounds__(256) void qproj_kernel(
    const float* __restrict__ h_tilde, const float* __restrict__ c_t,
    const float* __restrict__ Waq, const float* __restrict__ ba)
{
    __shared__ float As[16][64];
    __shared__ float Bs[16][64];
    const int t  = threadIdx.x;
    const int tx = t & 15, ty = t >> 4;
    const int b0 = blockIdx.x * 64;
    const int g0 = blockIdx.y * 64;

    float acc[4][4] = {};

    for (int k0 = 0; k0 < 2 * HD; k0 += 16) {
        #pragma unroll
        for (int i = 0; i < 4; i++) {
            int idx = t + i * 256;
            int r = idx >> 4, c = idx & 15;
            int j = k0 + c;
            As[c][r] = (j < HD) ? h_tilde[(b0 + r) * HD + j]
                                : c_t[(b0 + r) * HD + (j - HD)];
            Bs[c][r] = Waq[(g0 + r) * (2 * HD) + j];
        }
        __syncthreads();
        #pragma unroll
        for (int k = 0; k < 16; k++) {
            float4 av = *reinterpret_cast<const float4*>(&As[k][ty * 4]);
            float4 bv = *reinterpret_cast<const float4*>(&Bs[k][tx * 4]);
            float a[4] = {av.x, av.y, av.z, av.w};
            float bb[4] = {bv.x, bv.y, bv.z, bv.w};
            #pragma unroll
            for (int i = 0; i < 4; i++)
                #pragma unroll
                for (int jj = 0; jj < 4; jj++)
                    acc[i][jj] = fmaf(a[i], bb[jj], acc[i][jj]);
        }
        __syncthreads();
    }

    #pragma unroll
    for (int i = 0; i < 4; i++)
        #pragma unroll
        for (int jj = 0; jj < 4; jj++)
            g_qproj[(b0 + ty * 4 + i) * HD + (g0 + tx * 4 + jj)] =
                acc[i][jj] + ba[g0 + tx * 4 + jj];
}

// ---------------------------------------------------------------------------
// K2 (dominant): for each row m=(b,d), N-slice g0..g0+127:
//   partial_s = sum_g v[g] * tanh( hproj[m,g] + qproj[b,g] )   -> atomicAdd
// GEMM M=262144 N=512 K=512. CTA tile 128x128x16, 256 thr, 8x8 microtile,
// accumulators packed in f32x2 pairs along rows (FFMA2 = 2x fp32 throughput).
// ---------------------------------------------------------------------------
#define BK 16
__global__ __launch_bounds__(256, 2) void score_kernel(
    const float* __restrict__ hh, const float* __restrict__ Wah,
    const float* __restrict__ v_t)
{
    __shared__ float As[BK][128];
    __shared__ float Bs[BK][128];
    const int t  = threadIdx.x;
    const int tx = t & 15, ty = t >> 4;
    const int m0 = blockIdx.x * 128;   // row tile: (b,d) flattened
    const int g0 = blockIdx.y * 128;   // output-hidden tile

    u64 pacc[4][8];
    #pragma unroll
    for (int i = 0; i < 4; i++)
        #pragma unroll
        for (int j = 0; j < 8; j++) pacc[i][j] = 0ULL;

    for (int k0 = 0; k0 < HD; k0 += BK) {
        // stage A (h_history rows) and B (Wah rows) tiles, transposed to [k][mn]
        #pragma unroll
        for (int i = 0; i < 2; i++) {
            int f  = t + i * 256;      // float4 index within 128x16 tile
            int r  = f >> 2;           // row 0..127
            int c4 = (f & 3) * 4;      // k-col 0,4,8,12
            float4 v = *reinterpret_cast<const float4*>(
                &hh[(size_t)(m0 + r) * HD + k0 + c4]);
            As[c4 + 0][r] = v.x; As[c4 + 1][r] = v.y;
            As[c4 + 2][r] = v.z; As[c4 + 3][r] = v.w;
            float4 w = *reinterpret_cast<const float4*>(
                &Wah[(size_t)(g0 + r) * HD + k0 + c4]);
            Bs[c4 + 0][r] = w.x; Bs[c4 + 1][r] = w.y;
            Bs[c4 + 2][r] = w.z; Bs[c4 + 3][r] = w.w;
        }
        __syncthreads();
        #pragma unroll
        for (int k = 0; k < BK; k++) {
            // A: 8 rows as 4 packed f32x2 pairs (no repacking needed)
            ulonglong2 a01 = *reinterpret_cast<const ulonglong2*>(&As[k][ty * 8]);
            ulonglong2 a23 = *reinterpret_cast<const ulonglong2*>(&As[k][ty * 8 + 4]);
            u64 pa[4] = {a01.x, a01.y, a23.x, a23.y};
            // B: 8 cols, each duplicated into both lanes
            float4 b0v = *reinterpret_cast<const float4*>(&Bs[k][tx * 8]);
            float4 b1v = *reinterpret_cast<const float4*>(&Bs[k][tx * 8 + 4]);
            u64 bd[8];
            bd[0] = pk2(b0v.x, b0v.x); bd[1] = pk2(b0v.y, b0v.y);
            bd[2] = pk2(b0v.z, b0v.z); bd[3] = pk2(b0v.w, b0v.w);
            bd[4] = pk2(b1v.x, b1v.x); bd[5] = pk2(b1v.y, b1v.y);
            bd[6] = pk2(b1v.z, b1v.z); bd[7] = pk2(b1v.w, b1v.w);
            #pragma unroll
            for (int i = 0; i < 4; i++)
                #pragma unroll
                for (int j = 0; j < 8; j++)
                    fma2(pacc[i][j], pa[i], bd[j]);
        }
        __syncthreads();
    }

    // Epilogue: tanh + weighted reduce over g within this 128-wide N slice.
    // Tile rows m0..m0+127 all belong to one batch b (128 | 256).
    const int b = m0 / DH;
    float qp[8], vv[8];
    #pragma unroll
    for (int j = 0; j < 8; j++) {
        int g = g0 + tx * 8 + j;
        qp[j] = g_qproj[b * HD + g];
        vv[j] = v_t[g];
    }
    float local[8];
    #pragma unroll
    for (int rr = 0; rr < 8; rr++) local[rr] = 0.0f;
    #pragma unroll
    for (int i = 0; i < 4; i++) {
        #pragma unroll
        for (int j = 0; j < 8; j++) {
            float2 v2 = upk(pacc[i][j]);
            local[2 * i]     += vv[j] * fast_tanh(v2.x + qp[j]);
            local[2 * i + 1] += vv[j] * fast_tanh(v2.y + qp[j]);
        }
    }
    // reduce the 8-col partials across the 16 tx lanes (width-16 segments)
    #pragma unroll
    for (int rr = 0; rr < 8; rr++) {
        float val = local[rr];
        val += __shfl_down_sync(0xffffffffu, val, 8, 16);
        val += __shfl_down_sync(0xffffffffu, val, 4, 16);
        val += __shfl_down_sync(0xffffffffu, val, 2, 16);
        val += __shfl_down_sync(0xffffffffu, val, 1, 16);
        if (tx == 0)
            atomicAdd(&g_s[m0 + ty * 8 + rr], val);
    }
}

// ---------------------------------------------------------------------------
// K3: softmax over d (D=256) per batch row -> alpha output
// ---------------------------------------------------------------------------
__global__ __launch_bounds__(DH) void softmax_kernel(float* __restrict__ alpha_out)
{
    __shared__ float red[DH];
    const int b = blockIdx.x, d = threadIdx.x;
    float x = g_s[b * DH + d];
    red[d] = x;
    __syncthreads();
    for (int s = DH / 2; s > 0; s >>= 1) {
        if (d < s) red[d] = fmaxf(red[d], red[d + s]);
        __syncthreads();
    }
    float mx = red[0];
    __syncthreads();
    float e = __expf(x - mx);
    red[d] = e;
    __syncthreads();
    for (int s = DH / 2; s > 0; s >>= 1) {
        if (d < s) red[d] += red[d + s];
        __syncthreads();
    }
    alpha_out[b * DH + d] = e / red[0];
}

// ---------------------------------------------------------------------------
// K4: e_t[b,h] = sum_d alpha[b,d] * h_history[b,d,h]  (memory bound)
// ---------------------------------------------------------------------------
__global__ __launch_bounds__(HD) void et_kernel(
    const float* __restrict__ hh, const float* __restrict__ alpha,
    float* __restrict__ e_out)
{
    __shared__ float al[DH];
    const int b = blockIdx.x, h = threadIdx.x;
    if (h < DH) al[h] = alpha[b * DH + h];
    __syncthreads();
    const float* base = hh + (size_t)b * DH * HD + h;
    float acc = 0.0f;
    #pragma unroll 8
    for (int d = 0; d < DH; d++)
        acc = fmaf(al[d], base[(size_t)d * HD], acc);
    e_out[b * HD + h] = acc;
}

// ---------------------------------------------------------------------------
// launch: inputs per metadata order:
// 0 h_tilde [B,H] | 1 c_t [B,H] | 2 h_history [B,D,H] | 3 Waq [H,2H]
// 4 Wah [H,H] | 5 ba [H] | 6 v_t [H]   out = [e_t (B*H) | alpha (B*D)]
// ---------------------------------------------------------------------------
extern "C" void kernel_launch(void* const* d_in, const int* in_sizes, int n_in,
                              void* d_out, int out_size)
{
    const float* h_tilde = (const float*)d_in[0];
    const float* c_t     = (const float*)d_in[1];
    const float* hh      = (const float*)d_in[2];
    const float* Waq     = (const float*)d_in[3];
    const float* Wah     = (const float*)d_in[4];
    const float* ba      = (const float*)d_in[5];
    const float* v_t     = (const float*)d_in[6];

    float* out       = (float*)d_out;
    float* e_out     = out;               // [B, H]
    float* alpha_out = out + BSZ * HD;    // [B, D]

    zero_s_kernel<<<(BSZ * DH) / 256, 256>>>();

    dim3 g1(BSZ / 64, HD / 64);
    qproj_kernel<<<g1, 256>>>(h_tilde, c_t, Waq, ba);

    dim3 g2((BSZ * DH) / 128, HD / 128);
    score_kernel<<<g2, 256>>>(hh, Wah, v_t);

    softmax_kernel<<<BSZ, DH>>>(alpha_out);

    et_kernel<<<BSZ, HD>>>(hh, alpha_out, e_out);
}

// round 3
// speedup vs baseline: 1.8283x; 1.8283x over previous
#include <cuda_runtime.h>
#include <cuda_bf16.h>
#include <cstdint>

#define BSZ 1024
#define HD  512
#define DH  256
#define BD  (BSZ*DH)

typedef unsigned long long u64;

// ---------------------------------------------------------------------------
// scratch (__device__ globals; no runtime allocation allowed)
// ---------------------------------------------------------------------------
__device__ float g_qproj[BSZ * HD];                // q_proj + ba
__device__ float g_s[BD];                          // logits
__device__ __nv_bfloat16 g_hh_hi[(size_t)BD * HD]; // h_history split high
__device__ __nv_bfloat16 g_hh_lo[(size_t)BD * HD]; // h_history split low
__device__ __nv_bfloat16 g_w_hi[HD * HD];          // Wah split high
__device__ __nv_bfloat16 g_w_lo[HD * HD];          // Wah split low

// ---------------------------------------------------------------------------
// helpers
// ---------------------------------------------------------------------------
__device__ __forceinline__ uint32_t smem_u32(const void* p) {
    uint32_t a;
    asm("{ .reg .u64 t; cvta.to.shared.u64 t, %1; cvt.u32.u64 %0, t; }"
        : "=r"(a) : "l"(p));
    return a;
}
__device__ __forceinline__ void cpa16(uint32_t dst, const void* src) {
    asm volatile("cp.async.cg.shared.global [%0], [%1], 16;" :: "r"(dst), "l"(src));
}
__device__ __forceinline__ void mma16816(float* c, const uint32_t* a, const uint32_t* b) {
    asm volatile(
        "mma.sync.aligned.m16n8k16.row.col.f32.bf16.bf16.f32 "
        "{%0,%1,%2,%3}, {%4,%5,%6,%7}, {%8,%9}, {%0,%1,%2,%3};"
        : "+f"(c[0]), "+f"(c[1]), "+f"(c[2]), "+f"(c[3])
        : "r"(a[0]), "r"(a[1]), "r"(a[2]), "r"(a[3]), "r"(b[0]), "r"(b[1]));
}
__device__ __forceinline__ float fast_tanh(float x) {
    float e = __expf(2.0f * x);
    return 1.0f - 2.0f / (e + 1.0f);
}

// ---------------------------------------------------------------------------
// K0: zero logits
// ---------------------------------------------------------------------------
__global__ void zero_s_kernel() {
    int i = blockIdx.x * blockDim.x + threadIdx.x;
    if (i < BD) g_s[i] = 0.0f;
}

// ---------------------------------------------------------------------------
// converts: fp32 -> bf16 hi/lo split
// ---------------------------------------------------------------------------
__global__ __launch_bounds__(256) void convert_hh_kernel(const float* __restrict__ x) {
    int i = blockIdx.x * blockDim.x + threadIdx.x;
    float4 v = reinterpret_cast<const float4*>(x)[i];
    float vv[4] = {v.x, v.y, v.z, v.w};
    __nv_bfloat16 h[4], l[4];
#pragma unroll
    for (int j = 0; j < 4; j++) {
        h[j] = __float2bfloat16_rn(vv[j]);
        l[j] = __float2bfloat16_rn(vv[j] - __bfloat162float(h[j]));
    }
    __nv_bfloat162* hi2 = reinterpret_cast<__nv_bfloat162*>(g_hh_hi);
    __nv_bfloat162* lo2 = reinterpret_cast<__nv_bfloat162*>(g_hh_lo);
    hi2[2 * i]     = __halves2bfloat162(h[0], h[1]);
    hi2[2 * i + 1] = __halves2bfloat162(h[2], h[3]);
    lo2[2 * i]     = __halves2bfloat162(l[0], l[1]);
    lo2[2 * i + 1] = __halves2bfloat162(l[2], l[3]);
}

__global__ __launch_bounds__(256) void convert_w_kernel(const float* __restrict__ x) {
    int i = blockIdx.x * blockDim.x + threadIdx.x;
    float4 v = reinterpret_cast<const float4*>(x)[i];
    float vv[4] = {v.x, v.y, v.z, v.w};
    __nv_bfloat16 h[4], l[4];
#pragma unroll
    for (int j = 0; j < 4; j++) {
        h[j] = __float2bfloat16_rn(vv[j]);
        l[j] = __float2bfloat16_rn(vv[j] - __bfloat162float(h[j]));
    }
    __nv_bfloat162* hi2 = reinterpret_cast<__nv_bfloat162*>(g_w_hi);
    __nv_bfloat162* lo2 = reinterpret_cast<__nv_bfloat162*>(g_w_lo);
    hi2[2 * i]     = __halves2bfloat162(h[0], h[1]);
    hi2[2 * i + 1] = __halves2bfloat162(h[2], h[3]);
    lo2[2 * i]     = __halves2bfloat162(l[0], l[1]);
    lo2[2 * i + 1] = __halves2bfloat162(l[2], l[3]);
}

// ---------------------------------------------------------------------------
// K1: q_proj (small fp32 GEMM)
// ---------------------------------------------------------------------------
__global__ __launch_bounds__(256) void qproj_kernel(
    const float* __restrict__ h_tilde, const float* __restrict__ c_t,
    const float* __restrict__ Waq, const float* __restrict__ ba)
{
    __shared__ float As[16][64];
    __shared__ float Bs[16][64];
    const int t  = threadIdx.x;
    const int tx = t & 15, ty = t >> 4;
    const int b0 = blockIdx.x * 64;
    const int g0 = blockIdx.y * 64;

    float acc[4][4] = {};

    for (int k0 = 0; k0 < 2 * HD; k0 += 16) {
#pragma unroll
        for (int i = 0; i < 4; i++) {
            int idx = t + i * 256;
            int r = idx >> 4, c = idx & 15;
            int j = k0 + c;
            As[c][r] = (j < HD) ? h_tilde[(b0 + r) * HD + j]
                                : c_t[(b0 + r) * HD + (j - HD)];
            Bs[c][r] = Waq[(g0 + r) * (2 * HD) + j];
        }
        __syncthreads();
#pragma unroll
        for (int k = 0; k < 16; k++) {
            float4 av = *reinterpret_cast<const float4*>(&As[k][ty * 4]);
            float4 bv = *reinterpret_cast<const float4*>(&Bs[k][tx * 4]);
            float a[4] = {av.x, av.y, av.z, av.w};
            float bb[4] = {bv.x, bv.y, bv.z, bv.w};
#pragma unroll
            for (int i = 0; i < 4; i++)
#pragma unroll
                for (int jj = 0; jj < 4; jj++)
                    acc[i][jj] = fmaf(a[i], bb[jj], acc[i][jj]);
        }
        __syncthreads();
    }

#pragma unroll
    for (int i = 0; i < 4; i++)
#pragma unroll
        for (int jj = 0; jj < 4; jj++)
            g_qproj[(b0 + ty * 4 + i) * HD + (g0 + tx * 4 + jj)] =
                acc[i][jj] + ba[g0 + tx * 4 + jj];
}

// ---------------------------------------------------------------------------
// K2 (dominant): HMMA score kernel.
// CTA 128(M)x128(N), K=512 in chunks of 32, cp.async double buffer.
// bf16x3 split products, fp32 accum. Fused tanh/v-dot epilogue -> atomicAdd.
// SMEM row stride 40 halves (80B) -> conflict-free direct LDS fragment loads.
// ---------------------------------------------------------------------------
#define SSTR   40            // smem row stride (halves)
#define TILE_H (128 * SSTR)  // 5120 halves per 128x32 tile
#define STAGE_H (4 * TILE_H) // Ah, Al, Bh, Bl
#define NCHUNK 16            // 512 / 32

__global__ __launch_bounds__(256, 1) void score_mma_kernel(const float* __restrict__ v_t)
{
    extern __shared__ __nv_bfloat16 sm[];
    __shared__ float v_sh[128], qp_sh[128];

    const int t = threadIdx.x;
    const int l = t & 31, wid = t >> 5;
    const int warp_m = wid & 3;       // 0..3 -> M offset 32*warp_m
    const int warp_n = wid >> 2;      // 0..1 -> N offset 64*warp_n
    const int q  = l >> 2;            // 0..7
    const int c2 = (l & 3) * 2;       // 0,2,4,6

    const int g0 = blockIdx.x * 128;  // fast dim -> A-tile L2 reuse across 4 CTAs
    const int m0 = blockIdx.y * 128;
    const int b  = m0 / DH;

    if (t < 128) {
        v_sh[t]  = v_t[g0 + t];
        qp_sh[t] = g_qproj[b * HD + g0 + t];
    }

    const __nv_bfloat16* srcA_hi = g_hh_hi + (size_t)m0 * HD;
    const __nv_bfloat16* srcA_lo = g_hh_lo + (size_t)m0 * HD;
    const __nv_bfloat16* srcB_hi = g_w_hi + (size_t)g0 * HD;
    const __nv_bfloat16* srcB_lo = g_w_lo + (size_t)g0 * HD;

    const uint32_t smem_base = smem_u32(sm);

    float acc[2][8][4];
#pragma unroll
    for (int mt = 0; mt < 2; mt++)
#pragma unroll
        for (int nt = 0; nt < 8; nt++)
#pragma unroll
            for (int e = 0; e < 4; e++) acc[mt][nt][e] = 0.0f;

    // stage loader: 4 tiles (Ah,Al,Bh,Bl) of 128 rows x 32 halves (64B/row)
    auto load_chunk = [&](int ch, int st) {
        const uint32_t base = smem_base + (uint32_t)st * STAGE_H * 2;
        const int k0 = ch * 32;
#pragma unroll
        for (int j = 0; j < 8; j++) {
            const int tile = j >> 1;                 // compile-time after unroll
            const int u   = t + (j & 1) * 256;       // 0..511 within tile
            const int rr  = u >> 2, seg = u & 3;
            const uint32_t dst = base + (uint32_t)(tile * TILE_H + rr * SSTR) * 2
                                      + (uint32_t)seg * 16;
            const __nv_bfloat16* src =
                (tile == 0 ? srcA_hi : tile == 1 ? srcA_lo :
                 tile == 2 ? srcB_hi : srcB_lo)
                + (size_t)rr * HD + k0 + seg * 8;
            cpa16(dst, src);
        }
        asm volatile("cp.async.commit_group;" ::: "memory");
    };

    auto compute = [&](int st) {
        const uint32_t sb = (uint32_t)st * STAGE_H;
#pragma unroll
        for (int ks = 0; ks < 2; ks++) {
            const int kb = ks * 16;
            uint32_t a_hi[2][4], a_lo[2][4], b_hi[8][2], b_lo[8][2];
#pragma unroll
            for (int mt = 0; mt < 2; mt++) {
                const int row = warp_m * 32 + mt * 16 + q;
                const __nv_bfloat16* Ah = sm + sb + 0 * TILE_H + row * SSTR + kb + c2;
                const __nv_bfloat16* Al = sm + sb + 1 * TILE_H + row * SSTR + kb + c2;
                a_hi[mt][0] = *(const uint32_t*)(Ah);
                a_hi[mt][1] = *(const uint32_t*)(Ah + 8 * SSTR);
                a_hi[mt][2] = *(const uint32_t*)(Ah + 8);
                a_hi[mt][3] = *(const uint32_t*)(Ah + 8 * SSTR + 8);
                a_lo[mt][0] = *(const uint32_t*)(Al);
                a_lo[mt][1] = *(const uint32_t*)(Al + 8 * SSTR);
                a_lo[mt][2] = *(const uint32_t*)(Al + 8);
                a_lo[mt][3] = *(const uint32_t*)(Al + 8 * SSTR + 8);
            }
#pragma unroll
            for (int nt = 0; nt < 8; nt++) {
                const int n = warp_n * 64 + nt * 8 + q;
                const __nv_bfloat16* Bh = sm + sb + 2 * TILE_H + n * SSTR + kb + c2;
                const __nv_bfloat16* Bl = sm + sb + 3 * TILE_H + n * SSTR + kb + c2;
                b_hi[nt][0] = *(const uint32_t*)(Bh);
                b_hi[nt][1] = *(const uint32_t*)(Bh + 8);
                b_lo[nt][0] = *(const uint32_t*)(Bl);
                b_lo[nt][1] = *(const uint32_t*)(Bl + 8);
            }
            // 3 split products; same-acc reuse separated by 16 MMAs
#pragma unroll
            for (int nt = 0; nt < 8; nt++)
#pragma unroll
                for (int mt = 0; mt < 2; mt++)
                    mma16816(acc[mt][nt], a_hi[mt], b_hi[nt]);
#pragma unroll
            for (int nt = 0; nt < 8; nt++)
#pragma unroll
                for (int mt = 0; mt < 2; mt++)
                    mma16816(acc[mt][nt], a_hi[mt], b_lo[nt]);
#pragma unroll
            for (int nt = 0; nt < 8; nt++)
#pragma unroll
                for (int mt = 0; mt < 2; mt++)
                    mma16816(acc[mt][nt], a_lo[mt], b_hi[nt]);
        }
    };

    load_chunk(0, 0);
#pragma unroll 1
    for (int i = 0; i < NCHUNK; i++) {
        if (i + 1 < NCHUNK) {
            load_chunk(i + 1, (i + 1) & 1);
            asm volatile("cp.async.wait_group 1;" ::: "memory");
        } else {
            asm volatile("cp.async.wait_group 0;" ::: "memory");
        }
        __syncthreads();
        compute(i & 1);
        __syncthreads();
    }

    // epilogue: tanh + v-dot, quad reduce, atomicAdd per row
#pragma unroll
    for (int mt = 0; mt < 2; mt++) {
        float rs0 = 0.0f, rs1 = 0.0f;
#pragma unroll
        for (int nt = 0; nt < 8; nt++) {
            const int gbase = warp_n * 64 + nt * 8 + c2;
            const float vq0 = v_sh[gbase],     qq0 = qp_sh[gbase];
            const float vq1 = v_sh[gbase + 1], qq1 = qp_sh[gbase + 1];
            rs0 += vq0 * fast_tanh(acc[mt][nt][0] + qq0);
            rs0 += vq1 * fast_tanh(acc[mt][nt][1] + qq1);
            rs1 += vq0 * fast_tanh(acc[mt][nt][2] + qq0);
            rs1 += vq1 * fast_tanh(acc[mt][nt][3] + qq1);
        }
        rs0 += __shfl_xor_sync(0xffffffffu, rs0, 1);
        rs0 += __shfl_xor_sync(0xffffffffu, rs0, 2);
        rs1 += __shfl_xor_sync(0xffffffffu, rs1, 1);
        rs1 += __shfl_xor_sync(0xffffffffu, rs1, 2);
        if ((l & 3) == 0) {
            const int rowb = m0 + warp_m * 32 + mt * 16 + q;
            atomicAdd(&g_s[rowb],     rs0);
            atomicAdd(&g_s[rowb + 8], rs1);
        }
    }
}

// ---------------------------------------------------------------------------
// K3: softmax over d
// ---------------------------------------------------------------------------
__global__ __launch_bounds__(DH) void softmax_kernel(float* __restrict__ alpha_out)
{
    __shared__ float red[DH];
    const int b = blockIdx.x, d = threadIdx.x;
    float x = g_s[b * DH + d];
    red[d] = x;
    __syncthreads();
    for (int s = DH / 2; s > 0; s >>= 1) {
        if (d < s) red[d] = fmaxf(red[d], red[d + s]);
        __syncthreads();
    }
    float mx = red[0];
    __syncthreads();
    float e = __expf(x - mx);
    red[d] = e;
    __syncthreads();
    for (int s = DH / 2; s > 0; s >>= 1) {
        if (d < s) red[d] += red[d + s];
        __syncthreads();
    }
    alpha_out[b * DH + d] = e / red[0];
}

// ---------------------------------------------------------------------------
// K4: e_t = alpha . h_history (memory bound)
// ---------------------------------------------------------------------------
__global__ __launch_bounds__(HD) void et_kernel(
    const float* __restrict__ hh, const float* __restrict__ alpha,
    float* __restrict__ e_out)
{
    __shared__ float al[DH];
    const int b = blockIdx.x, h = threadIdx.x;
    if (h < DH) al[h] = alpha[b * DH + h];
    __syncthreads();
    const float* basep = hh + (size_t)b * DH * HD + h;
    float acc = 0.0f;
#pragma unroll 8
    for (int d = 0; d < DH; d++)
        acc = fmaf(al[d], basep[(size_t)d * HD], acc);
    e_out[b * HD + h] = acc;
}

// ---------------------------------------------------------------------------
// launch
// inputs: 0 h_tilde | 1 c_t | 2 h_history | 3 Waq | 4 Wah | 5 ba | 6 v_t
// out = [e_t (B*H) | alpha (B*D)]
// ---------------------------------------------------------------------------
extern "C" void kernel_launch(void* const* d_in, const int* in_sizes, int n_in,
                              void* d_out, int out_size)
{
    const float* h_tilde = (const float*)d_in[0];
    const float* c_t     = (const float*)d_in[1];
    const float* hh      = (const float*)d_in[2];
    const float* Waq     = (const float*)d_in[3];
    const float* Wah     = (const float*)d_in[4];
    const float* ba      = (const float*)d_in[5];
    const float* v_t     = (const float*)d_in[6];

    float* out       = (float*)d_out;
    float* e_out     = out;               // [B, H]
    float* alpha_out = out + BSZ * HD;    // [B, D]

    static bool attr_set = false;
    if (!attr_set) {
        cudaFuncSetAttribute(score_mma_kernel,
                             cudaFuncAttributeMaxDynamicSharedMemorySize,
                             2 * STAGE_H * 2);
        attr_set = true;
    }

    zero_s_kernel<<<BD / 256, 256>>>();

    convert_hh_kernel<<<((size_t)BD * HD / 4) / 256, 256>>>(hh);
    convert_w_kernel<<<(HD * HD / 4) / 256, 256>>>(Wah);

    dim3 g1(BSZ / 64, HD / 64);
    qproj_kernel<<<g1, 256>>>(h_tilde, c_t, Waq, ba);

    dim3 g2(HD / 128, BD / 128);   // g0 fastest -> A-tile L2 reuse
    score_mma_kernel<<<g2, 256, 2 * STAGE_H * 2>>>(v_t);

    softmax_kernel<<<BSZ, DH>>>(alpha_out);

    et_kernel<<<BSZ, HD>>>(hh, alpha_out, e_out);
}

// round 4
// speedup vs baseline: 2.0356x; 1.1134x over previous
#include <cuda_runtime.h>
#include <cuda_bf16.h>
#include <cstdint>

#define BSZ 1024
#define HD  512
#define DH  256
#define BD  (BSZ*DH)

typedef unsigned long long u64;

// ---------------------------------------------------------------------------
// scratch (__device__ globals; no runtime allocation allowed)
// ---------------------------------------------------------------------------
__device__ float g_qproj[BSZ * HD];        // q_proj + ba
__device__ float g_part[8 * BD];           // per (g-tile, warp_n) logit partials
__device__ __nv_bfloat16 g_w_hi[HD * HD];  // Wah split high
__device__ __nv_bfloat16 g_w_lo[HD * HD];  // Wah split low

// ---------------------------------------------------------------------------
// helpers
// ---------------------------------------------------------------------------
__device__ __forceinline__ uint32_t smem_u32(const void* p) {
    uint32_t a;
    asm("{ .reg .u64 t; cvta.to.shared.u64 t, %1; cvt.u32.u64 %0, t; }"
        : "=r"(a) : "l"(p));
    return a;
}
__device__ __forceinline__ void cpa16(uint32_t dst, const void* src) {
    asm volatile("cp.async.cg.shared.global [%0], [%1], 16;" :: "r"(dst), "l"(src));
}
__device__ __forceinline__ void ldsm4(uint32_t* r, uint32_t addr) {
    asm volatile("ldmatrix.sync.aligned.m8n8.x4.shared.b16 {%0,%1,%2,%3}, [%4];"
        : "=r"(r[0]), "=r"(r[1]), "=r"(r[2]), "=r"(r[3]) : "r"(addr));
}
__device__ __forceinline__ void mma16816(float* c, const uint32_t* a, const uint32_t* b) {
    asm volatile(
        "mma.sync.aligned.m16n8k16.row.col.f32.bf16.bf16.f32 "
        "{%0,%1,%2,%3}, {%4,%5,%6,%7}, {%8,%9}, {%0,%1,%2,%3};"
        : "+f"(c[0]), "+f"(c[1]), "+f"(c[2]), "+f"(c[3])
        : "r"(a[0]), "r"(a[1]), "r"(a[2]), "r"(a[3]), "r"(b[0]), "r"(b[1]));
}
__device__ __forceinline__ float fast_tanh(float x) {
    float e = __expf(2.0f * x);
    return 1.0f - 2.0f / (e + 1.0f);
}

// ---------------------------------------------------------------------------
// convert_w: Wah fp32 -> bf16 hi/lo split (1 MB, trivial)
// ---------------------------------------------------------------------------
__global__ __launch_bounds__(256) void convert_w_kernel(const float* __restrict__ x) {
    int i = blockIdx.x * blockDim.x + threadIdx.x;
    float4 v = reinterpret_cast<const float4*>(x)[i];
    float vv[4] = {v.x, v.y, v.z, v.w};
    __nv_bfloat16 h[4], l[4];
#pragma unroll
    for (int j = 0; j < 4; j++) {
        h[j] = __float2bfloat16_rn(vv[j]);
        l[j] = __float2bfloat16_rn(vv[j] - __bfloat162float(h[j]));
    }
    __nv_bfloat162* hi2 = reinterpret_cast<__nv_bfloat162*>(g_w_hi);
    __nv_bfloat162* lo2 = reinterpret_cast<__nv_bfloat162*>(g_w_lo);
    hi2[2 * i]     = __halves2bfloat162(h[0], h[1]);
    hi2[2 * i + 1] = __halves2bfloat162(h[2], h[3]);
    lo2[2 * i]     = __halves2bfloat162(l[0], l[1]);
    lo2[2 * i + 1] = __halves2bfloat162(l[2], l[3]);
}

// ---------------------------------------------------------------------------
// qproj: M=1024 N=512 K=1024 fp32; 32x64 tiles -> 256 CTAs (occupancy fix)
// ---------------------------------------------------------------------------
#define QBK 32
__global__ __launch_bounds__(128) void qproj_kernel(
    const float* __restrict__ h_tilde, const float* __restrict__ c_t,
    const float* __restrict__ Waq, const float* __restrict__ ba)
{
    __shared__ float As[QBK][36];   // [k][m], 32 rows used
    __shared__ float Bs[QBK][68];   // [k][n], 64 rows used
    const int t  = threadIdx.x;
    const int tx = t & 15, ty = t >> 4;   // tx: 16 -> 64 n, ty: 8 -> 32 m
    const int b0 = blockIdx.x * 32;
    const int g0 = blockIdx.y * 64;

    float acc[4][4] = {};

    for (int k0 = 0; k0 < 2 * HD; k0 += QBK) {
        // A: 32x32 = 1024 elems / 128 thr = 8 ; B: 64x32 = 2048 / 128 = 16
#pragma unroll
        for (int i = 0; i < 8; i++) {
            int idx = t + i * 128;
            int r = idx >> 5, c = idx & 31;
            int j = k0 + c;
            As[c][r] = (j < HD) ? h_tilde[(b0 + r) * HD + j]
                                : c_t[(b0 + r) * HD + (j - HD)];
        }
#pragma unroll
        for (int i = 0; i < 16; i++) {
            int idx = t + i * 128;
            int r = idx >> 5, c = idx & 31;
            Bs[c][r] = Waq[(g0 + r) * (2 * HD) + k0 + c];
        }
        __syncthreads();
#pragma unroll
        for (int k = 0; k < QBK; k++) {
            float4 av = *reinterpret_cast<const float4*>(&As[k][ty * 4]);
            float4 bv = *reinterpret_cast<const float4*>(&Bs[k][tx * 4]);
            float a[4] = {av.x, av.y, av.z, av.w};
            float bb[4] = {bv.x, bv.y, bv.z, bv.w};
#pragma unroll
            for (int i = 0; i < 4; i++)
#pragma unroll
                for (int jj = 0; jj < 4; jj++)
                    acc[i][jj] = fmaf(a[i], bb[jj], acc[i][jj]);
        }
        __syncthreads();
    }

#pragma unroll
    for (int i = 0; i < 4; i++)
#pragma unroll
        for (int jj = 0; jj < 4; jj++)
            g_qproj[(b0 + ty * 4 + i) * HD + (g0 + tx * 4 + jj)] =
                acc[i][jj] + ba[g0 + tx * 4 + jj];
}

// ---------------------------------------------------------------------------
// separator no-op (aligns score as the 4th launch for ncu capture)
// ---------------------------------------------------------------------------
__global__ void sep_kernel() {}

// ---------------------------------------------------------------------------
// score: HMMA GEMM with in-kernel fp32->bf16 hi/lo split of h_history.
// CTA 128(M)x128(N), K=512 in chunks of 32. A: LDG float4 -> split -> STS
// (register double-buffer). B: cp.async bf16 (pre-split). ldmatrix frags.
// Epilogue: tanh + v-dot, quad reduce, plain store into g_part slice.
// ---------------------------------------------------------------------------
#define SSTR    40            // smem row stride in halves (80 B)
#define TILE_H  (128 * SSTR)  // halves per 128x32 tile
#define STAGE_H (4 * TILE_H)  // Ah, Al, Bh, Bl
#define NCHUNK  16            // 512/32

__global__ __launch_bounds__(256) void score_mma_kernel(
    const float* __restrict__ hh, const float* __restrict__ v_t)
{
    extern __shared__ __nv_bfloat16 sm[];
    __shared__ float v_sh[128], qp_sh[128];

    const int t = threadIdx.x;
    const int l = t & 31, wid = t >> 5;
    const int warp_m = wid & 3;       // M offset 32*warp_m
    const int warp_n = wid >> 2;      // N offset 64*warp_n
    const int c2 = (l & 3) * 2;

    const int g0 = blockIdx.x * 128;  // fast dim -> A-tile L2 reuse (4 CTAs)
    const int m0 = blockIdx.y * 128;
    const int b  = m0 / DH;

    if (t < 128) {
        v_sh[t]  = v_t[g0 + t];
        qp_sh[t] = g_qproj[b * HD + g0 + t];
    }

    const float*         srcA = hh + (size_t)m0 * HD;
    const __nv_bfloat16* srcBh = g_w_hi + (size_t)g0 * HD;
    const __nv_bfloat16* srcBl = g_w_lo + (size_t)g0 * HD;

    const uint32_t smem_base = smem_u32(sm);
    char* smc = reinterpret_cast<char*>(sm);

    float acc[2][8][4];
#pragma unroll
    for (int mt = 0; mt < 2; mt++)
#pragma unroll
        for (int nt = 0; nt < 8; nt++)
#pragma unroll
            for (int e = 0; e < 4; e++) acc[mt][nt][e] = 0.0f;

    // A chunk: 128 rows x 32 fp32 -> 1024 float4 tasks / 256 thr = 4
    auto ldgA = [&](int ch, float4* r) {
        const int k0 = ch * 32;
#pragma unroll
        for (int j = 0; j < 4; j++) {
            int task = t + j * 256;
            int row = task >> 3, sg = task & 7;
            r[j] = *reinterpret_cast<const float4*>(
                srcA + (size_t)row * HD + k0 + sg * 4);
        }
    };
    // split + STS into Ah/Al tiles of stage st
    auto stsA = [&](int st, const float4* r) {
        const uint32_t base = (uint32_t)st * STAGE_H * 2;
#pragma unroll
        for (int j = 0; j < 4; j++) {
            int task = t + j * 256;
            int row = task >> 3, sg = task & 7;
            float4 v = r[j];
            __nv_bfloat162 h01 = __floats2bfloat162_rn(v.x, v.y);
            __nv_bfloat162 h23 = __floats2bfloat162_rn(v.z, v.w);
            __nv_bfloat162 l01 = __floats2bfloat162_rn(
                v.x - __bfloat162float(h01.x), v.y - __bfloat162float(h01.y));
            __nv_bfloat162 l23 = __floats2bfloat162_rn(
                v.z - __bfloat162float(h23.x), v.w - __bfloat162float(h23.y));
            uint2 hv = make_uint2(*(uint32_t*)&h01, *(uint32_t*)&h23);
            uint2 lv = make_uint2(*(uint32_t*)&l01, *(uint32_t*)&l23);
            uint32_t off = base + (uint32_t)(row * SSTR) * 2 + (uint32_t)sg * 8;
            *reinterpret_cast<uint2*>(smc + off)              = hv;
            *reinterpret_cast<uint2*>(smc + TILE_H * 2 + off) = lv;
        }
    };
    // B chunk: 2 tiles (hi, lo) of 128 rows x 32 halves -> 4 cpa16/thread
    auto cpB = [&](int ch, int st) {
        const uint32_t base = smem_base + (uint32_t)st * STAGE_H * 2;
        const int k0 = ch * 32;
#pragma unroll
        for (int j = 0; j < 2; j++) {
            int task = t + j * 256;          // 0..511
            int row = task >> 2, seg = task & 3;
            uint32_t off = (uint32_t)(row * SSTR) * 2 + (uint32_t)seg * 16;
            size_t so = (size_t)row * HD + k0 + seg * 8;
            cpa16(base + 2 * TILE_H * 2 + off, srcBh + so);
            cpa16(base + 3 * TILE_H * 2 + off, srcBl + so);
        }
        asm volatile("cp.async.commit_group;" ::: "memory");
    };

    auto compute = [&](int st) {
        const uint32_t sb = smem_base + (uint32_t)st * STAGE_H * 2;
#pragma unroll
        for (int ks = 0; ks < 2; ks++) {
            const int kb = ks * 16;
            uint32_t a_hi[2][4], a_lo[2][4], b_hi[4][4], b_lo[4][4];
#pragma unroll
            for (int mt = 0; mt < 2; mt++) {
                int row = warp_m * 32 + mt * 16 + (l & 7) + ((l >> 3) & 1) * 8;
                int col = kb + ((l >> 4) & 1) * 8;
                uint32_t off = (uint32_t)(row * SSTR + col) * 2;
                ldsm4(a_hi[mt], sb + off);
                ldsm4(a_lo[mt], sb + TILE_H * 2 + off);
            }
#pragma unroll
            for (int p = 0; p < 4; p++) {
                int n = warp_n * 64 + p * 16 + (l & 7) + ((l >> 4) & 1) * 8;
                int col = kb + ((l >> 3) & 1) * 8;
                uint32_t off = (uint32_t)(n * SSTR + col) * 2;
                ldsm4(b_hi[p], sb + 2 * TILE_H * 2 + off);
                ldsm4(b_lo[p], sb + 3 * TILE_H * 2 + off);
            }
            // b_hi[p][0..1] = frag nt=2p ; b_hi[p][2..3] = frag nt=2p+1
#pragma unroll
            for (int p = 0; p < 4; p++)
#pragma unroll
                for (int h = 0; h < 2; h++)
#pragma unroll
                    for (int mt = 0; mt < 2; mt++)
                        mma16816(acc[mt][2 * p + h], a_hi[mt], &b_hi[p][2 * h]);
#pragma unroll
            for (int p = 0; p < 4; p++)
#pragma unroll
                for (int h = 0; h < 2; h++)
#pragma unroll
                    for (int mt = 0; mt < 2; mt++)
                        mma16816(acc[mt][2 * p + h], a_hi[mt], &b_lo[p][2 * h]);
#pragma unroll
            for (int p = 0; p < 4; p++)
#pragma unroll
                for (int h = 0; h < 2; h++)
#pragma unroll
                    for (int mt = 0; mt < 2; mt++)
                        mma16816(acc[mt][2 * p + h], a_lo[mt], &b_hi[p][2 * h]);
        }
    };

    float4 regA[2][4];
    ldgA(0, regA[0]);
    cpB(0, 0);

#pragma unroll 2
    for (int i = 0; i < NCHUNK; i++) {
        const int s = i & 1;
        stsA(s, regA[s]);
        if (i + 1 < NCHUNK) {
            ldgA(i + 1, regA[s ^ 1]);
            cpB(i + 1, s ^ 1);
            asm volatile("cp.async.wait_group 1;" ::: "memory");
        } else {
            asm volatile("cp.async.wait_group 0;" ::: "memory");
        }
        __syncthreads();
        compute(s);
        __syncthreads();
    }

    // epilogue: tanh + v-dot, quad reduce, plain store into partial slice
    const int slice = blockIdx.x * 2 + warp_n;     // 0..7
    const int q = l >> 2;
#pragma unroll
    for (int mt = 0; mt < 2; mt++) {
        float rs0 = 0.0f, rs1 = 0.0f;
#pragma unroll
        for (int nt = 0; nt < 8; nt++) {
            const int gbase = warp_n * 64 + nt * 8 + c2;
            const float vq0 = v_sh[gbase],     qq0 = qp_sh[gbase];
            const float vq1 = v_sh[gbase + 1], qq1 = qp_sh[gbase + 1];
            rs0 += vq0 * fast_tanh(acc[mt][nt][0] + qq0);
            rs0 += vq1 * fast_tanh(acc[mt][nt][1] + qq1);
            rs1 += vq0 * fast_tanh(acc[mt][nt][2] + qq0);
            rs1 += vq1 * fast_tanh(acc[mt][nt][3] + qq1);
        }
        rs0 += __shfl_xor_sync(0xffffffffu, rs0, 1);
        rs0 += __shfl_xor_sync(0xffffffffu, rs0, 2);
        rs1 += __shfl_xor_sync(0xffffffffu, rs1, 1);
        rs1 += __shfl_xor_sync(0xffffffffu, rs1, 2);
        if ((l & 3) == 0) {
            const int rowb = m0 + warp_m * 32 + mt * 16 + q;
            g_part[slice * BD + rowb]     = rs0;
            g_part[slice * BD + rowb + 8] = rs1;
        }
    }
}

// ---------------------------------------------------------------------------
// softmax: sum 8 partial slices, then softmax over d
// ---------------------------------------------------------------------------
__global__ __launch_bounds__(DH) void softmax_kernel(float* __restrict__ alpha_out)
{
    __shared__ float red[DH];
    const int b = blockIdx.x, d = threadIdx.x;
    const int row = b * DH + d;
    float x = 0.0f;
#pragma unroll
    for (int s = 0; s < 8; s++) x += g_part[s * BD + row];
    red[d] = x;
    __syncthreads();
    for (int s = DH / 2; s > 0; s >>= 1) {
        if (d < s) red[d] = fmaxf(red[d], red[d + s]);
        __syncthreads();
    }
    float mx = red[0];
    __syncthreads();
    float e = __expf(x - mx);
    red[d] = e;
    __syncthreads();
    for (int s = DH / 2; s > 0; s >>= 1) {
        if (d < s) red[d] += red[d + s];
        __syncthreads();
    }
    alpha_out[row] = e / red[0];
}

// ---------------------------------------------------------------------------
// e_t = alpha . h_history (memory bound)
// ---------------------------------------------------------------------------
__global__ __launch_bounds__(HD) void et_kernel(
    const float* __restrict__ hh, const float* __restrict__ alpha,
    float* __restrict__ e_out)
{
    __shared__ float al[DH];
    const int b = blockIdx.x, h = threadIdx.x;
    if (h < DH) al[h] = alpha[b * DH + h];
    __syncthreads();
    const float* basep = hh + (size_t)b * DH * HD + h;
    float acc = 0.0f;
#pragma unroll 8
    for (int d = 0; d < DH; d++)
        acc = fmaf(al[d], basep[(size_t)d * HD], acc);
    e_out[b * HD + h] = acc;
}

// ---------------------------------------------------------------------------
// launch
// inputs: 0 h_tilde | 1 c_t | 2 h_history | 3 Waq | 4 Wah | 5 ba | 6 v_t
// out = [e_t (B*H) | alpha (B*D)]
// ---------------------------------------------------------------------------
extern "C" void kernel_launch(void* const* d_in, const int* in_sizes, int n_in,
                              void* d_out, int out_size)
{
    const float* h_tilde = (const float*)d_in[0];
    const float* c_t     = (const float*)d_in[1];
    const float* hh      = (const float*)d_in[2];
    const float* Waq     = (const float*)d_in[3];
    const float* Wah     = (const float*)d_in[4];
    const float* ba      = (const float*)d_in[5];
    const float* v_t     = (const float*)d_in[6];

    float* out       = (float*)d_out;
    float* e_out     = out;               // [B, H]
    float* alpha_out = out + BSZ * HD;    // [B, D]

    cudaFuncSetAttribute(score_mma_kernel,
                         cudaFuncAttributeMaxDynamicSharedMemorySize,
                         2 * STAGE_H * 2);

    convert_w_kernel<<<(HD * HD / 4) / 256, 256>>>(Wah);          // 1

    dim3 g1(BSZ / 32, HD / 64);
    qproj_kernel<<<g1, 128>>>(h_tilde, c_t, Waq, ba);             // 2

    sep_kernel<<<1, 32>>>();                                      // 3

    dim3 g2(HD / 128, BD / 128);   // g0 fastest -> A-tile L2 reuse
    score_mma_kernel<<<g2, 256, 2 * STAGE_H * 2>>>(hh, v_t);      // 4 (profiled)

    softmax_kernel<<<BSZ, DH>>>(alpha_out);                       // 5

    et_kernel<<<BSZ, HD>>>(hh, alpha_out, e_out);                 // 6
}